// round 11
// baseline (speedup 1.0000x reference)
#include <cuda_runtime.h>
#include <math.h>

// Problem constants (fixed by dataset)
#define TT 1600
#define NN 32
#define CC 512
#define SS 200
#define RINGR 32               // row ring slots (power of 2)
#define KST 6                  // trellis steps per barrier period
#define HALO 6                 // halo pair-lanes per warp
#define SPW 52                 // owned states per warp (26 pairs)
#define NFULL 266              // full periods: t = 1..1596
#define PAIRS 208
#define THREADS 256            // 8 warps, one example per CTA
#define LOG2E 1.4426950408889634f
#define ESENT (-(1 << 28))     // "empty pair" exponent sentinel

// ---- dynamic smem layout ----
#define OFF_SHA   (RINGR * CC)                     // float index of shA
#define OFF_SHE   (OFF_SHA * 4 + 2 * PAIRS * 8)    // byte offset of shE
#define SMEM_BYTES (OFF_SHE + 2 * PAIRS * 4)       // ~70.2 KB

__device__ float g_per_ex[NN];
__device__ unsigned int g_count;

__device__ __forceinline__ float ex2f(float x) {
    float y; asm("ex2.approx.ftz.f32 %0, %1;" : "=f"(y) : "f"(x)); return y;
}
// exact 2^k for k <= 0 (0 below normal range); k=0 -> 1
__device__ __forceinline__ float exp2neg(int k) {
    return (k <= -127) ? 0.0f : __uint_as_float((unsigned)(127 + k) << 23);
}
__device__ __forceinline__ void cp_async16(void* smem_dst, const void* gmem_src) {
    unsigned s = (unsigned)__cvta_generic_to_shared(smem_dst);
    asm volatile("cp.async.cg.shared.global [%0], [%1], 16;" :: "r"(s), "l"(gmem_src));
}
__device__ __forceinline__ void cp_commit() { asm volatile("cp.async.commit_group;"); }
template<int N>
__device__ __forceinline__ void cp_wait() { asm volatile("cp.async.wait_group %0;" :: "n"(N)); }

__global__ void __launch_bounds__(THREADS, 1)
ctc_kernel(const float* __restrict__ lp,       // (T, N, C)
           const int*   __restrict__ targets,  // (N, S)
           const int*   __restrict__ input_lens,
           const int*   __restrict__ target_lens,
           float*       __restrict__ out)
{
    extern __shared__ float smem[];
    const int tid  = threadIdx.x;
    const int lw   = tid >> 5;          // warp 0..7
    const int lane = tid & 31;
    const int n    = blockIdx.x;

    float*  rowbuf = smem;                                   // [RINGR][CC]
    float2* shA    = (float2*)(smem + OFF_SHA);              // [2][PAIRS]
    int*    shE    = (int*)((char*)smem + OFF_SHE);          // [2][PAIRS]

    const int  sB    = SPW * lw + 2 * (lane - HALO);   // even state of my pair
    const bool owner = (lane >= HALO);
    const int  pB    = sB >> 1;                        // valid when sB >= 0

    const size_t NC = (size_t)NN * CC;
    const float* __restrict__ base = lp + (size_t)n * CC;
    const int tl = target_lens[n];
    const int il = input_lens[n];

    // per-pair invariants (clamped safe for ALL lanes; out-of-range garbage harmless)
    const int idx = min(max(sB, 0) >> 1, SS - 1);
    const int myExt = targets[n * SS + idx];
    bool allow = false;
    if (sB >= 2 && sB < 400)
        allow = (myExt != targets[n * SS + idx - 1]);

    // ---- alpha_0 in linear domain with per-thread exponent ----
    // Sub-range lanes (sB<0) start at exactly 0 and stay 0 unmasked:
    // their lower neighbors are 0 (lane 0 shfl_up returns own value).
    float aE = 0.0f, aO = 0.0f;
    int   E  = ESENT;
    if (sB == 0) {
        aE = ex2f(base[0] * LOG2E);
        if (tl >= 1) aO = ex2f(base[myExt] * LOG2E);
        E = 0;
    }
    if (owner) { shA[PAIRS + pB] = make_float2(aE, aO); shE[PAIRS + pB] = E; }

    // ---- prologue: rows for periods 0..2 (rows 1..18), 16B cp.async ----
    const int g   = tid >> 7;          // row group (0/1)
    const int cid = tid & 127;         // 16B chunk within row
#pragma unroll
    for (int q = 0; q < 3; ++q) {
#pragma unroll
        for (int j = 0; j < 3; ++j) {
            const int r = KST * q + 1 + 3 * g + j;
            cp_async16(&rowbuf[(r & (RINGR - 1)) * CC + cid * 4],
                       base + (size_t)r * NC + cid * 4);
        }
        cp_commit();
    }

    // ================== main loop: 266 unmasked full periods ==================
    for (int p = 0; p < NFULL; ++p) {
        cp_wait<2>();
        __syncthreads();      // rows of period p + prev-period shA/shE visible

        // ---- halo refresh (value + exponent) ----
        const int prevb = (p & 1) ^ 1;
        if (lane < HALO && sB >= 0) {
            const float2 v = shA[prevb * PAIRS + pB];
            aE = v.x; aO = v.y;
            E  = shE[prevb * PAIRS + pB];
        }

        // ---- per-warp inclusive max-scan of E -> M (monotone in lane) ----
        int M = E;
#pragma unroll
        for (int o = 1; o < 32; o <<= 1) {
            const int v = __shfl_up_sync(0xffffffffu, M, o);
            if (lane >= o) M = max(M, v);
        }
        const float fSelf = exp2neg(E - M);     // <= 1 (E <= M)
        aE *= fSelf; aO *= fSelf; E = M;
        const int   Mnb  = __shfl_up_sync(0xffffffffu, M, 1);
        const float fNb  = exp2neg(Mnb - M);    // <= 1; lane 0 gets own M -> 1
        const float fNbA = allow ? fNb : 0.0f;

        const int t0 = KST * p;
        // gather + convert emits (only MUFU work; off critical chain)
        float eB[KST], eO[KST];
#pragma unroll
        for (int k = 0; k < KST; ++k) {
            const float* row = rowbuf + (size_t)((t0 + 1 + k) & (RINGR - 1)) * CC;
            eB[k] = ex2f(row[0]     * LOG2E);
            eO[k] = ex2f(row[myExt] * LOG2E);
        }

        // ---- 6 trellis steps: 1 shfl + 2 FMA + 1 ADD + 2 MUL, no selects ----
#pragma unroll
        for (int k = 0; k < KST; ++k) {
            const float nbO = __shfl_up_sync(0xffffffffu, aO, 1);  // alpha(sB-1)
            const float sE  = fmaf(nbO, fNb,  aE);
            const float sO  = fmaf(nbO, fNbA, aE + aO);
            aE = sE * eB[k];
            aO = sO * eO[k];
        }

        // ---- prefetch rows for period p+3 ----
        {
            const int r0 = KST * (p + 3) + 1 + 3 * g;
#pragma unroll
            for (int j = 0; j < 3; ++j) {
                const int r = r0 + j;
                if (r < TT)
                    cp_async16(&rowbuf[(r & (RINGR - 1)) * CC + cid * 4],
                               base + (size_t)r * NC + cid * 4);
            }
            cp_commit();
        }

        // ---- per-thread exact power-of-2 renorm ----
        const float m = fmaxf(aE, aO);
        if (m > 0.0f) {
            const int e = (int)((__float_as_uint(m) >> 23) & 255) - 127;
            const float sc = __uint_as_float((unsigned)(127 - e) << 23);  // 2^{-e}
            aE *= sc; aO *= sc; E += e;
        } else {
            E = ESENT;
        }

        // publish for next period's halo
        if (owner) {
            shA[(p & 1) * PAIRS + pB] = make_float2(aE, aO);
            shE[(p & 1) * PAIRS + pB] = E;
        }
    }
    // period 265 published into buffer 1

    // ================== masked tail: t = 1597..1599 ==================
    cp_wait<0>();
    __syncthreads();
    {
        if (lane < HALO && sB >= 0) {
            const float2 v = shA[1 * PAIRS + pB];
            aE = v.x; aO = v.y;
            E  = shE[1 * PAIRS + pB];
        }
        int M = E;
#pragma unroll
        for (int o = 1; o < 32; o <<= 1) {
            const int v = __shfl_up_sync(0xffffffffu, M, o);
            if (lane >= o) M = max(M, v);
        }
        const float fSelf = exp2neg(E - M);
        aE *= fSelf; aO *= fSelf; E = M;
        const int   Mnb  = __shfl_up_sync(0xffffffffu, M, 1);
        const float fNb  = exp2neg(Mnb - M);
        const float fNbA = allow ? fNb : 0.0f;

#pragma unroll
        for (int j = 0; j < 3; ++j) {
            const int t = 1597 + j;
            const float* row = rowbuf + (size_t)(t & (RINGR - 1)) * CC;
            const float eBt = ex2f(row[0]     * LOG2E);
            const float eOt = ex2f(row[myExt] * LOG2E);
            const float nbO = __shfl_up_sync(0xffffffffu, aO, 1);
            const float sE  = fmaf(nbO, fNb,  aE);
            const float sO  = fmaf(nbO, fNbA, aE + aO);
            const bool act = (t < il);
            aE = act ? sE * eBt : aE;
            aO = act ? sO * eOt : aO;
        }

        // final publish into buffer 0
        if (owner) {
            shA[pB] = make_float2(aE, aO);
            shE[pB] = E;
        }
    }
    __syncthreads();

    // ---- readout (double precision, once) + fused mean reduction ----
    if (tid == 0) {
        const float2 vL = shA[tl];          // pair tl: state 2*tl (final blank)
        const int    EL = shE[tl];
        float aPv = 0.0f; int EP = 0;
        if (tl > 0) { aPv = shA[tl - 1].y; EP = shE[tl - 1]; }  // state 2*tl-1
        const double l1 = (vL.x > 0.0f) ? (double)EL + log2((double)vL.x) : -1e30;
        const double l2 = (aPv  > 0.0f) ? (double)EP + log2((double)aPv) : -1e30;
        const double mm = fmax(l1, l2);
        const double lo = fmin(l1, l2);
        double loss = -0.6931471805599453 * (mm + log2(1.0 + exp2(lo - mm)));
        if (!(loss < 1e29)) loss = 0.0;                    // zero_infinity (+NaN kill)
        const float norm = sqrtf(fmaxf((float)tl, 1.0f));  // ALPHA = 0.5
        ((volatile float*)g_per_ex)[n] = (float)loss / norm;
        __threadfence();
        const unsigned old = atomicAdd(&g_count, 1u);
        if ((old % NN) == (NN - 1)) {                      // last example of replay
            __threadfence();
            float acc = 0.0f;
#pragma unroll
            for (int i = 0; i < NN; ++i) acc += ((volatile float*)g_per_ex)[i];
            out[0] = acc / (float)NN;
        }
    }
}

extern "C" void kernel_launch(void* const* d_in, const int* in_sizes, int n_in,
                              void* d_out, int out_size)
{
    const float* log_probs   = (const float*)d_in[0];
    const int*   targets     = (const int*)d_in[1];
    const int*   input_lens  = (const int*)d_in[2];
    const int*   target_lens = (const int*)d_in[3];
    float* out = (float*)d_out;

    cudaFuncSetAttribute(ctc_kernel,
                         cudaFuncAttributeMaxDynamicSharedMemorySize, SMEM_BYTES);
    ctc_kernel<<<NN, THREADS, SMEM_BYTES>>>(log_probs, targets,
                                            input_lens, target_lens, out);
}

// round 12
// speedup vs baseline: 1.5234x; 1.5234x over previous
#include <cuda_runtime.h>
#include <math.h>

// Problem constants (fixed by dataset)
#define TT 1600
#define NN 32
#define CC 512
#define SS 200
#define RINGR 64               // row ring slots (power of 2)
#define KST 12                 // trellis steps per barrier period
#define NFULL 133              // full periods: t = 1..1596 (+3-step masked tail)
#define SLOTP 104              // float4 alpha slots per buffer (states 0..415)
#define THREADS 128            // 4 warps, 4 states per thread
#define LOG2E 1.4426950408889634f
#define ESENT (-(1 << 28))     // "empty slot" exponent sentinel

// ---- dynamic smem layout (bytes) ----
#define OFF_SHA   (RINGR * CC * 4)                  // float4 shA[2][SLOTP]
#define OFF_SHE   (OFF_SHA + 2 * SLOTP * 16)        // int shE[2][SLOTP]
#define SMEM_BYTES (OFF_SHE + 2 * SLOTP * 4)        // 135232 B

__device__ float g_per_ex[NN];
__device__ unsigned int g_count;

__device__ __forceinline__ float ex2f(float x) {
    float y; asm("ex2.approx.ftz.f32 %0, %1;" : "=f"(y) : "f"(x)); return y;
}
// exact 2^k for k <= 0 (0 below normal range); k=0 -> 1
__device__ __forceinline__ float exp2neg(int k) {
    return (k <= -127) ? 0.0f : __uint_as_float((unsigned)(127 + k) << 23);
}
__device__ __forceinline__ void cp_async16(void* smem_dst, const void* gmem_src) {
    unsigned s = (unsigned)__cvta_generic_to_shared(smem_dst);
    asm volatile("cp.async.cg.shared.global [%0], [%1], 16;" :: "r"(s), "l"(gmem_src));
}
__device__ __forceinline__ void cp_commit() { asm volatile("cp.async.commit_group;"); }
template<int N>
__device__ __forceinline__ void cp_wait() { asm volatile("cp.async.wait_group %0;" :: "n"(N)); }

__global__ void __launch_bounds__(THREADS, 1)
ctc_kernel(const float* __restrict__ lp,       // (T, N, C)
           const int*   __restrict__ targets,  // (N, S)
           const int*   __restrict__ input_lens,
           const int*   __restrict__ target_lens,
           float*       __restrict__ out)
{
    extern __shared__ float smem[];
    float*  rowbuf = smem;                                   // [RINGR][CC]
    float4* shA4   = (float4*)((char*)smem + OFF_SHA);       // [2][SLOTP]
    int*    shE    = (int*)((char*)smem + OFF_SHE);          // [2][SLOTP]

    const int tid  = threadIdx.x;
    const int lw   = tid >> 5;          // warp 0..3
    const int lane = tid & 31;
    const int n    = blockIdx.x;

    // thread holds states sBase..sBase+3; lanes 0..5 = halo (2*KST = 24 states)
    const int  sBase = 104 * lw + 4 * (lane - 6);
    const int  slot  = 26 * lw + lane - 6;     // sBase >> 2 (valid when sBase >= 0)
    const bool owner = (lane >= 6);

    const size_t NC = (size_t)NN * CC;
    const float* __restrict__ base = lp + (size_t)n * CC;
    const int tl = target_lens[n];
    const int il = input_lens[n];

    // ---- per-thread label invariants (clamped; garbage lanes harmless) ----
    const int i4   = max(sBase, 0) >> 2;
    const int idx1 = min(2 * i4,     SS - 1);   // label of state 4i+1
    const int idx3 = min(2 * i4 + 1, SS - 1);   // label of state 4i+3
    const int ext1 = targets[n * SS + idx1];
    const int ext3 = targets[n * SS + idx3];
    const float al3f = (ext3 != ext1) ? 1.0f : 0.0f;   // skip for state 4i+3
    bool allow1 = false;                                // skip for state 4i+1
    if (sBase >= 4) allow1 = (ext1 != targets[n * SS + idx1 - 1]);

    // ---- alpha_0 in linear domain with per-thread exponent ----
    float aE0 = 0.0f, aO1 = 0.0f, aE2 = 0.0f, aO3 = 0.0f;
    int   E   = ESENT;
    if (sBase == 0) {
        aE0 = ex2f(base[0] * LOG2E);
        if (tl >= 1) aO1 = ex2f(base[ext1] * LOG2E);
        E = 0;
    }
    if (owner) {
        shA4[SLOTP + slot] = make_float4(aE0, aO1, aE2, aO3);  // buffer 1
        shE [SLOTP + slot] = E;
    }

    // ---- prologue: rows for periods 0..2 (rows 1..36) ----
#pragma unroll
    for (int q = 0; q < 3; ++q) {
#pragma unroll
        for (int k = 1; k <= KST; ++k) {
            const int r = KST * q + k;
            cp_async16(&rowbuf[(r & (RINGR - 1)) * CC + tid * 4],
                       base + (size_t)r * NC + tid * 4);
        }
        cp_commit();
    }

    float fNb = 1.0f, fNbA1 = 0.0f;

    // ================== main loop: 133 full periods of 12 steps ==================
    for (int p = 0; p < NFULL; ++p) {
        cp_wait<2>();
        __syncthreads();      // rows of period p + prev-period shA/shE visible

        // ---- halo refresh (value + exponent) ----
        const int prevb = (p & 1) ^ 1;
        if (lane < 6 && sBase >= 0) {
            const float4 v = shA4[prevb * SLOTP + slot];
            aE0 = v.x; aO1 = v.y; aE2 = v.z; aO3 = v.w;
            E   = shE[prevb * SLOTP + slot];
        }

        // ---- per-warp inclusive max-scan of E -> M (monotone in lane) ----
        int M = E;
#pragma unroll
        for (int o = 1; o < 32; o <<= 1) {
            const int v = __shfl_up_sync(0xffffffffu, M, o);
            if (lane >= o) M = max(M, v);
        }
        const float fSelf = exp2neg(E - M);      // <= 1 (E <= M)
        aE0 *= fSelf; aO1 *= fSelf; aE2 *= fSelf; aO3 *= fSelf; E = M;
        const int Mnb = __shfl_up_sync(0xffffffffu, M, 1);
        fNb   = exp2neg(Mnb - M);                // <= 1; lane 0 gets own M -> 1
        fNbA1 = allow1 ? fNb : 0.0f;

        const int t0 = KST * p;
        // ---- 3 chunks of 4 steps; emits prefetched per chunk ----
#pragma unroll
        for (int c = 0; c < 3; ++c) {
            float eB[4], e1[4], e3[4];
#pragma unroll
            for (int j = 0; j < 4; ++j) {
                const float* row = rowbuf + (size_t)((t0 + 1 + 4 * c + j) & (RINGR - 1)) * CC;
                eB[j] = ex2f(row[0]    * LOG2E);   // blank (serves both even states)
                e1[j] = ex2f(row[ext1] * LOG2E);
                e3[j] = ex2f(row[ext3] * LOG2E);
            }
#pragma unroll
            for (int j = 0; j < 4; ++j) {
                const float nb = __shfl_up_sync(0xffffffffu, aO3, 1);  // alpha(sBase-1)
                const float u0 = fmaf(nb,  fNb,   aE0);
                const float u1 = fmaf(nb,  fNbA1, aO1 + aE0);
                const float u2 = aE2 + aO1;
                const float u3 = fmaf(aO1, al3f,  aO3 + aE2);
                aE0 = u0 * eB[j];
                aO1 = u1 * e1[j];
                aE2 = u2 * eB[j];
                aO3 = u3 * e3[j];
            }
        }

        // ---- prefetch rows for period p+3 ----
        {
            const int r0 = KST * (p + 3) + 1;
#pragma unroll
            for (int k = 0; k < KST; ++k) {
                const int r = r0 + k;
                if (r < TT)
                    cp_async16(&rowbuf[(r & (RINGR - 1)) * CC + tid * 4],
                               base + (size_t)r * NC + tid * 4);
            }
            cp_commit();   // empty groups keep accounting aligned
        }

        // ---- per-thread exact power-of-2 renorm ----
        const float m = fmaxf(fmaxf(aE0, aO1), fmaxf(aE2, aO3));
        if (m > 0.0f) {
            const int e = (int)((__float_as_uint(m) >> 23) & 255) - 127;
            const float sc = __uint_as_float((unsigned)(127 - e) << 23);  // 2^{-e}
            aE0 *= sc; aO1 *= sc; aE2 *= sc; aO3 *= sc; E += e;
        } else {
            E = ESENT;
        }

        // publish for next period's halo
        if (owner) {
            shA4[(p & 1) * SLOTP + slot] = make_float4(aE0, aO1, aE2, aO3);
            shE [(p & 1) * SLOTP + slot] = E;
        }
    }
    // period 132 published into buffer 0

    // ================== masked tail: t = 1597..1599 ==================
    cp_wait<0>();
    __syncthreads();
    {
        if (lane < 6 && sBase >= 0) {
            const float4 v = shA4[0 * SLOTP + slot];
            aE0 = v.x; aO1 = v.y; aE2 = v.z; aO3 = v.w;
            E   = shE[0 * SLOTP + slot];
        }
        int M = E;
#pragma unroll
        for (int o = 1; o < 32; o <<= 1) {
            const int v = __shfl_up_sync(0xffffffffu, M, o);
            if (lane >= o) M = max(M, v);
        }
        const float fSelf = exp2neg(E - M);
        aE0 *= fSelf; aO1 *= fSelf; aE2 *= fSelf; aO3 *= fSelf; E = M;
        const int Mnb = __shfl_up_sync(0xffffffffu, M, 1);
        fNb   = exp2neg(Mnb - M);
        fNbA1 = allow1 ? fNb : 0.0f;

#pragma unroll
        for (int j = 0; j < 3; ++j) {
            const int t = 1597 + j;
            const float* row = rowbuf + (size_t)(t & (RINGR - 1)) * CC;
            const float eBt = ex2f(row[0]    * LOG2E);
            const float e1t = ex2f(row[ext1] * LOG2E);
            const float e3t = ex2f(row[ext3] * LOG2E);
            const float nb = __shfl_up_sync(0xffffffffu, aO3, 1);
            const float u0 = fmaf(nb,  fNb,   aE0);
            const float u1 = fmaf(nb,  fNbA1, aO1 + aE0);
            const float u2 = aE2 + aO1;
            const float u3 = fmaf(aO1, al3f,  aO3 + aE2);
            const bool act = (t < il);
            aE0 = act ? u0 * eBt : aE0;
            aO1 = act ? u1 * e1t : aO1;
            aE2 = act ? u2 * eBt : aE2;
            aO3 = act ? u3 * e3t : aO3;
        }

        // final publish into buffer 1
        if (owner) {
            shA4[SLOTP + slot] = make_float4(aE0, aO1, aE2, aO3);
            shE [SLOTP + slot] = E;
        }
    }
    __syncthreads();

    // ---- readout (double precision, once) + fused mean reduction ----
    if (tid == 0) {
        const int q1 = 2 * tl;                      // final blank state
        const float v1 = ((const float*)&shA4[SLOTP + (q1 >> 2)])[q1 & 3];
        const int   E1 = shE[SLOTP + (q1 >> 2)];
        float v2 = 0.0f; int E2 = 0;
        if (tl > 0) {
            const int q2 = q1 - 1;                  // final label state
            v2 = ((const float*)&shA4[SLOTP + (q2 >> 2)])[q2 & 3];
            E2 = shE[SLOTP + (q2 >> 2)];
        }
        const double l1 = (v1 > 0.0f) ? (double)E1 + log2((double)v1) : -1e30;
        const double l2 = (v2 > 0.0f) ? (double)E2 + log2((double)v2) : -1e30;
        const double mm = fmax(l1, l2);
        const double lo = fmin(l1, l2);
        double loss = -0.6931471805599453 * (mm + log2(1.0 + exp2(lo - mm)));
        if (!(loss < 1e29)) loss = 0.0;                    // zero_infinity (+NaN kill)
        const float norm = sqrtf(fmaxf((float)tl, 1.0f));  // ALPHA = 0.5
        ((volatile float*)g_per_ex)[n] = (float)loss / norm;
        __threadfence();
        const unsigned old = atomicAdd(&g_count, 1u);
        if ((old % NN) == (NN - 1)) {                      // last example of replay
            __threadfence();
            float acc = 0.0f;
#pragma unroll
            for (int i = 0; i < NN; ++i) acc += ((volatile float*)g_per_ex)[i];
            out[0] = acc / (float)NN;
        }
    }
}

extern "C" void kernel_launch(void* const* d_in, const int* in_sizes, int n_in,
                              void* d_out, int out_size)
{
    const float* log_probs   = (const float*)d_in[0];
    const int*   targets     = (const int*)d_in[1];
    const int*   input_lens  = (const int*)d_in[2];
    const int*   target_lens = (const int*)d_in[3];
    float* out = (float*)d_out;

    cudaFuncSetAttribute(ctc_kernel,
                         cudaFuncAttributeMaxDynamicSharedMemorySize, SMEM_BYTES);
    ctc_kernel<<<NN, THREADS, SMEM_BYTES>>>(log_probs, targets,
                                            input_lens, target_lens, out);
}